// round 16
// baseline (speedup 1.0000x reference)
#include <cuda_runtime.h>
#include <cuda_bf16.h>

#define NBX 512
#define NBY 512
#define KK  5
#define TARGET_AREA 0.9f
#define MS  520                     // padded map row stride (floats)
#define MAPSZ (512 * MS + 16)       // max used idx 511*520+515

#define GRID_F   1184               // 8 blocks/SM x 148 SMs, all resident
#define TPB_F    256
#define FIN_NB   512                // finishing blocks (tiles 16x x 32y)

// ---- static device scratch (no runtime allocation allowed) ----
// M copies: logical (x,y) stored at idx x*MS + (y - k) + 4   (copy k)
// T copies: logical (x,y) stored at idx y*MS + (x - k) + 4   (copy k, transposed)
__device__ __align__(16) float g_M[4][MAPSZ];
__device__ __align__(16) float g_T[4][MAPSZ];
__device__ float g_sum;             // reset by last finish ticket
__device__ int   g_done;
__device__ int   g_bar;             // grid barrier; reset by last finish ticket

__device__ __forceinline__ void red_add_v4(float* a, float v0, float v1, float v2, float v3) {
    asm volatile("red.global.add.v4.f32 [%0], {%1, %2, %3, %4};"
                 :: "l"(a), "f"(v0), "f"(v1), "f"(v2), "f"(v3) : "memory");
}
__device__ __forceinline__ void red_add_f(float* a, float v) {
    asm volatile("red.global.add.f32 [%0], %1;" :: "l"(a), "f"(v) : "memory");
}

__device__ __forceinline__ float bell1(float d0, float k, float s, float a,
                                       float cb, float p1, float p2) {
    float d = fabsf(d0 - k);
    float v;
    if (d < p1)      v = s * (1.0f - a * d * d);
    else if (d < p2) { float t = d - p2; v = cb * t * t; }
    else             v = 0.0f;
    return v;
}

__device__ __forceinline__ void pot5(float coord, float s, int s0, float* p) {
    float ctr = coord + 0.5f * s;
    float a   = 4.0f / ((s + 2.0f) * (s + 4.0f));
    float cb  = s * (2.0f / (s + 4.0f));
    float p1  = 0.5f * s + 1.0f;
    float p2  = 0.5f * s + 2.0f;
    float d0  = ctr - ((float)s0 + 0.5f);
#pragma unroll
    for (int k = 0; k < KK; k++)
        p[k] = bell1(d0, (float)k, s, a, cb, p1, p2);
}

__device__ __forceinline__ int strip5(float* q) {
    int sft = 0;
#pragma unroll
    for (int t = 0; t < 4; t++) {
        if (q[0] == 0.0f) {
            q[0] = q[1]; q[1] = q[2]; q[2] = q[3]; q[3] = q[4]; q[4] = 0.0f;
            sft++;
        }
    }
    return sft;
}

// Per-node deposit (register-lean R15 body): <=5 row-v4 REDs + (P=.5) T-v4
// + (P~.125) corner. 5.125 requests/node avg — at the covering bound.
__device__ __forceinline__ void deposit_node(float x, float y, float sx, float sy) {
    int sx0 = min(max((int)floorf(x - 2.0f), 0), NBX - KK);
    int sy0 = min(max((int)floorf(y - 2.0f), 0), NBY - KK);

    float q[KK];
    pot5(y, sy, sy0, q);
    int ys = sy0 + strip5(q);
    float colv = q[4];
    float* Mk = g_M[ys & 3];
    int ycol = (ys & ~3) + 4;

    float ax  = 4.0f / ((sx + 2.0f) * (sx + 4.0f));
    float cbx = sx * (2.0f / (sx + 4.0f));
    float p1x = 0.5f * sx + 1.0f;
    float p2x = 0.5f * sx + 2.0f;
    float d0x = (x + 0.5f * sx) - ((float)sx0 + 0.5f);

#pragma unroll
    for (int r = 0; r < KK; r++) {
        float vx = bell1(d0x, (float)r, sx, ax, cbx, p1x, p2x);
        if (vx != 0.0f)
            red_add_v4(Mk + (sx0 + r) * MS + ycol,
                       vx * q[0], vx * q[1], vx * q[2], vx * q[3]);
    }

    if (colv != 0.0f) {
        float c[KK];
#pragma unroll
        for (int r = 0; r < KK; r++)
            c[r] = bell1(d0x, (float)r, sx, ax, cbx, p1x, p2x);
        int xs = sx0 + strip5(c);
        float corner = c[4];
        float* Tk = g_T[xs & 3];
        red_add_v4(Tk + (sy0 + 4) * MS + (xs & ~3) + 4,
                   colv * c[0], colv * c[1], colv * c[2], colv * c[3]);
        if (corner != 0.0f)
            red_add_f(&g_M[0][(sx0 + 4) * MS + (sy0 + 4) + 4], corner * colv);
    }
}

// ---------------------------------------------------------------------------
// Fused persistent kernel at scatter-saturating occupancy (8 x 256 per SM):
//   Phase A: grid-stride scatter  (64 warps/SM — measured at the REDG floor)
//   Phase B: grid barrier (all 1184 resident; non-finish blocks arrive+exit)
//   Phase C: blocks < 512 finish one 16x(32) tile each on warm SMs
// ---------------------------------------------------------------------------
__global__ void __launch_bounds__(TPB_F, 8) fused_kernel(
    const float* __restrict__ pos,
    const float* __restrict__ sxs,
    const float* __restrict__ sys,
    const float* __restrict__ initial,
    float* __restrict__ out,
    int n)
{
    __shared__ float ts[32][17];       // [y-local][x-local], conflict-free
    __shared__ float sd[8];

    const int tid = threadIdx.x;

    // ===== Phase A: scatter (grid-stride over nodes) =====
    for (int i = blockIdx.x * TPB_F + tid; i < n; i += GRID_F * TPB_F) {
        deposit_node(pos[i], pos[n + i], sxs[i], sys[i]);
    }

    // ===== Phase B: grid barrier =====
    __threadfence();
    __syncthreads();
    if (tid == 0) atomicAdd(&g_bar, 1);

    if (blockIdx.x >= FIN_NB) return;  // arrive-and-exit; finish handled below

    if (tid == 0) {
        while (atomicAdd(&g_bar, 0) < GRID_F) { __nanosleep(32); }
    }
    __syncthreads();

    // ===== Phase C: finish — tile b: x in [X0,X0+16), y in [Y0,Y0+32) =====
    const int b  = blockIdx.x;
    const int X0 = (b & 31) << 4;      // 32 x-tiles of width 16
    const int Y0 = (b >> 5) << 5;      // 16 y-tiles of height 32

    // --- T fold: thread (xl = tid&15, yl2 = tid>>4 in 0..15) does y = yl2, yl2+16
    {
        int xl = tid & 15;
        int yl = tid >> 4;             // 0..15
#pragma unroll
        for (int yy = 0; yy < 2; yy++) {
            int ygl = yl + 16 * yy;    // 0..31
            int tBase = (Y0 + ygl) * MS + X0 + xl;
            float s = g_T[0][tBase + 4] + g_T[1][tBase + 3]
                    + g_T[2][tBase + 2] + g_T[3][tBase + 1];
            ts[ygl][xl] = s;
        }
    }
    __syncthreads();

    // --- M fold + cost: warp w (0..7) covers x = 2w, 2w+1; y = lane (32-wide) ---
    float acc = 0.0f;
    {
        int lane = tid & 31;
        int w    = tid >> 5;           // 0..7
#pragma unroll
        for (int xx = 0; xx < 2; xx++) {
            int xl = w * 2 + xx;       // 0..15
            int xg = X0 + xl;
            int yg = Y0 + lane;
            int mBase = xg * MS + yg;
            float v = initial[xg * NBY + yg]
                    + g_M[0][mBase + 4] + g_M[1][mBase + 3]
                    + g_M[2][mBase + 2] + g_M[3][mBase + 1]
                    + ts[lane][xl];
            float d = v - TARGET_AREA;
            acc += d * d;
        }
    }

    // --- zero own regions (streaming stores, decoupled) ---
    {
        int xl = tid & 15;
        int yl = tid >> 4;
#pragma unroll
        for (int yy = 0; yy < 2; yy++) {
            int tBase = (Y0 + yl + 16 * yy) * MS + X0 + xl;
#pragma unroll
            for (int k = 0; k < 4; k++)
                g_T[k][tBase + 4 - k] = 0.0f;
        }
        int lane = tid & 31;
        int w    = tid >> 5;
#pragma unroll
        for (int xx = 0; xx < 2; xx++) {
            int mBase = (X0 + w * 2 + xx) * MS + (Y0 + lane);
#pragma unroll
            for (int k = 0; k < 4; k++)
                g_M[k][mBase + 4 - k] = 0.0f;
        }
    }

    // --- block reduce (8 warps) + ticketed out-write / full state reset ---
    int lane = tid & 31;
    int w    = tid >> 5;
#pragma unroll
    for (int off = 16; off > 0; off >>= 1)
        acc += __shfl_xor_sync(0xFFFFFFFF, acc, off);
    if (lane == 0) sd[w] = acc;
    __syncthreads();
    if (tid < 8) {
        float v = sd[tid];
#pragma unroll
        for (int off = 4; off > 0; off >>= 1)
            v += __shfl_xor_sync(0xFF, v, off);
        if (tid == 0) {
            atomicAdd(&g_sum, v);
            __threadfence();
            int t = atomicAdd(&g_done, 1);
            if (t == FIN_NB - 1) {     // all blocks already arrived at g_bar
                out[0] = g_sum;
                g_sum  = 0.0f;         // restore invariants for next replay
                g_done = 0;
                g_bar  = 0;
            }
        }
    }
}

// ---------------------------------------------------------------------------
extern "C" void kernel_launch(void* const* d_in, const int* in_sizes, int n_in,
                              void* d_out, int out_size) {
    const float* pos = (const float*)d_in[0];
    const float* sx  = (const float*)d_in[1];
    const float* sy  = (const float*)d_in[2];
    // d_in[3..8]: ax..cy — recomputed analytically; d_in[9..10]: bin centers — analytic
    const float* initial = (const float*)d_in[11];
    float* out = (float*)d_out;

    int n = in_sizes[1];

    fused_kernel<<<GRID_F, TPB_F>>>(pos, sx, sy, initial, out, n);
}

// round 17
// speedup vs baseline: 1.1304x; 1.1304x over previous
#include <cuda_runtime.h>
#include <cuda_bf16.h>

#define NBX 512
#define NBY 512
#define KK  5
#define TARGET_AREA 0.9f
#define MS  520                     // padded map row stride (floats)
#define MAPSZ (512 * MS + 16)       // max used idx 511*520+515

// ---- static device scratch (no runtime allocation allowed) ----
// M copies: logical (x,y) stored at idx x*MS + (y - k) + 4   (copy k)
// T copies: logical (x,y) stored at idx y*MS + (x - k) + 4   (copy k, transposed)
__device__ __align__(16) float g_M[4][MAPSZ];
__device__ __align__(16) float g_T[4][MAPSZ];
__device__ float g_sum;             // reset by finish's last block
__device__ int   g_done;

__device__ __forceinline__ void red_add_v4(float* a, float v0, float v1, float v2, float v3) {
    asm volatile("red.global.add.v4.f32 [%0], {%1, %2, %3, %4};"
                 :: "l"(a), "f"(v0), "f"(v1), "f"(v2), "f"(v3) : "memory");
}
__device__ __forceinline__ void red_add_f(float* a, float v) {
    asm volatile("red.global.add.f32 [%0], %1;" :: "l"(a), "f"(v) : "memory");
}

// single bell value at integer-offset k from window start
__device__ __forceinline__ float bell1(float d0, float k, float s, float a,
                                       float cb, float p1, float p2) {
    float d = fabsf(d0 - k);
    float v;
    if (d < p1)      v = s * (1.0f - a * d * d);
    else if (d < p2) { float t = d - p2; v = cb * t * t; }
    else             v = 0.0f;
    return v;
}

// 5 bell-potential values over window starting at s0 (zeros only at the ends)
__device__ __forceinline__ void pot5(float coord, float s, int s0, float* p) {
    float ctr = coord + 0.5f * s;
    float a   = 4.0f / ((s + 2.0f) * (s + 4.0f));
    float cb  = s * (2.0f / (s + 4.0f));
    float p1  = 0.5f * s + 1.0f;
    float p2  = 0.5f * s + 2.0f;
    float d0  = ctr - ((float)s0 + 0.5f);
#pragma unroll
    for (int k = 0; k < KK; k++)
        p[k] = bell1(d0, (float)k, s, a, cb, p1, p2);
}

// strip leading zeros from q[0..4] (shifting zeros in at the top); returns shift
__device__ __forceinline__ int strip5(float* q) {
    int sft = 0;
#pragma unroll
    for (int t = 0; t < 4; t++) {
        if (q[0] == 0.0f) {
            q[0] = q[1]; q[1] = q[2]; q[2] = q[3]; q[3] = q[4]; q[4] = 0.0f;
            sft++;
        }
    }
    return sft;
}

// ---------------------------------------------------------------------------
// Scatter (register-lean, 8 blocks/SM): per node <=5 row-v4 REDs +
// (P=.5) column T-v4 + (P~.125) corner. 5.125 requests/node — at the
// covering bound; measured at the REDG lane floor (1.3 cyc/lane/SM).
// ---------------------------------------------------------------------------
__global__ void __launch_bounds__(256, 8) scatter_kernel(
    const float* __restrict__ pos,
    const float* __restrict__ sxs,
    const float* __restrict__ sys,
    int n)
{
    int i = blockIdx.x * blockDim.x + threadIdx.x;
    if (i >= n) return;

    float x  = pos[i];
    float y  = pos[n + i];
    float sx = sxs[i];
    float sy = sys[i];

    int sx0 = min(max((int)floorf(x - 2.0f), 0), NBX - KK);
    int sy0 = min(max((int)floorf(y - 2.0f), 0), NBY - KK);

    // ---- y window: strip, v4 lanes + leftover column ----
    float q[KK];
    pot5(y, sy, sy0, q);
    int ys = sy0 + strip5(q);
    float colv = q[4];                 // nonzero only when shift==0 && width==5
    float* Mk = g_M[ys & 3];
    int ycol = (ys & ~3) + 4;

    // ---- x params (per-row value on the fly) ----
    float ax  = 4.0f / ((sx + 2.0f) * (sx + 4.0f));
    float cbx = sx * (2.0f / (sx + 4.0f));
    float p1x = 0.5f * sx + 1.0f;
    float p2x = 0.5f * sx + 2.0f;
    float d0x = (x + 0.5f * sx) - ((float)sx0 + 0.5f);

#pragma unroll
    for (int r = 0; r < KK; r++) {
        float vx = bell1(d0x, (float)r, sx, ax, cbx, p1x, p2x);
        if (vx != 0.0f)
            red_add_v4(Mk + (sx0 + r) * MS + ycol,
                       vx * q[0], vx * q[1], vx * q[2], vx * q[3]);
    }

    if (colv != 0.0f) {                // 5th column at logical y = sy0+4
        float c[KK];
#pragma unroll
        for (int r = 0; r < KK; r++)
            c[r] = bell1(d0x, (float)r, sx, ax, cbx, p1x, p2x);
        int xs = sx0 + strip5(c);
        float corner = c[4];
        float* Tk = g_T[xs & 3];
        red_add_v4(Tk + (sy0 + 4) * MS + (xs & ~3) + 4,
                   colv * c[0], colv * c[1], colv * c[2], colv * c[3]);
        if (corner != 0.0f)            // corner (sx0+4, sy0+4)
            red_add_f(&g_M[0][(sx0 + 4) * MS + (sy0 + 4) + 4], corner * colv);
    }
}

// ---------------------------------------------------------------------------
// Finish (R11 exact geometry — fastest measured): 256 blocks x 1024 threads,
// one 32x32 tile per block, all 9 global loads batched (__ldcg: L1 is
// per-launch-flushed on Blackwell, skip the pointless fill), 32-wide
// coalesced everywhere, own-region zeroing, plain launch (no PDL — measured
// slower with it).
// ---------------------------------------------------------------------------
__global__ void __launch_bounds__(1024) finish_kernel(
    const float* __restrict__ initial,
    float* __restrict__ out)
{
    __shared__ float ts[32][33];       // stride 33: conflict-free both ways
    __shared__ float sd[32];

    int b    = blockIdx.x;
    int X0   = (b & 15) << 5;
    int Y0   = (b >> 4) << 5;
    int tid  = threadIdx.x;
    int lane = tid & 31;
    int row  = tid >> 5;               // 0..31

    int tBase = (Y0 + row) * MS + X0 + lane;   // T: coalesced along x
    int xgM   = X0 + row;
    int mBase = xgM * MS + (Y0 + lane);        // M: coalesced along y
    int iIdx  = xgM * NBY + (Y0 + lane);

    // ---- all 9 independent loads back-to-back (one latency window) ----
    float t0 = __ldcg(&g_T[0][tBase + 4]);
    float t1 = __ldcg(&g_T[1][tBase + 3]);
    float t2 = __ldcg(&g_T[2][tBase + 2]);
    float t3 = __ldcg(&g_T[3][tBase + 1]);
    float m0 = __ldcg(&g_M[0][mBase + 4]);
    float m1 = __ldcg(&g_M[1][mBase + 3]);
    float m2 = __ldcg(&g_M[2][mBase + 2]);
    float m3 = __ldcg(&g_M[3][mBase + 1]);
    float i0 = __ldcg(&initial[iIdx]);

    // ---- T fold -> smem transpose ----
    ts[row][lane] = t0 + t1 + t2 + t3;
    __syncthreads();

    // ---- per-cell density + cost ----
    float v = i0 + m0 + m1 + m2 + m3 + ts[lane][row];
    float d = v - TARGET_AREA;
    float acc = d * d;

    // ---- zero own region (plain streaming stores, 32-wide) ----
#pragma unroll
    for (int k = 0; k < 4; k++)
        g_T[k][tBase + 4 - k] = 0.0f;
#pragma unroll
    for (int k = 0; k < 4; k++)
        g_M[k][mBase + 4 - k] = 0.0f;

    // ---- block reduce (32 warps) + ticketed final write / state reset ----
#pragma unroll
    for (int off = 16; off > 0; off >>= 1)
        acc += __shfl_xor_sync(0xFFFFFFFF, acc, off);
    if (lane == 0) sd[row] = acc;
    __syncthreads();
    if (tid < 32) {
        float v2 = sd[tid];
#pragma unroll
        for (int off = 16; off > 0; off >>= 1)
            v2 += __shfl_xor_sync(0xFFFFFFFF, v2, off);
        if (tid == 0) {
            atomicAdd(&g_sum, v2);
            __threadfence();
            int t = atomicAdd(&g_done, 1);
            if (t == (int)gridDim.x - 1) {
                out[0] = g_sum;
                g_sum  = 0.0f;         // restore invariants for next replay
                g_done = 0;
            }
        }
    }
}

// ---------------------------------------------------------------------------
extern "C" void kernel_launch(void* const* d_in, const int* in_sizes, int n_in,
                              void* d_out, int out_size) {
    const float* pos = (const float*)d_in[0];
    const float* sx  = (const float*)d_in[1];
    const float* sy  = (const float*)d_in[2];
    // d_in[3..8]: ax..cy — recomputed analytically; d_in[9..10]: bin centers — analytic
    const float* initial = (const float*)d_in[11];
    float* out = (float*)d_out;

    int n = in_sizes[1];

    scatter_kernel<<<(n + 255) / 256, 256>>>(pos, sx, sy, n);
    finish_kernel<<<256, 1024>>>(initial, out);
}